// round 12
// baseline (speedup 1.0000x reference)
#include <cuda_runtime.h>

// EEG_SimpleLSM: 3-layer LIF winner-take-all liquid state machine.
// x: [256, 32, 4000] f32, W1: [64,32], W2: [128,64]. Output: exp(pre_v2@T-1) [256,128].
//
// ROUND 12 = ROUND 11 + single-collective argmax. Cross-round fit says every
// warp collective (REDUX and BALLOT alike) costs ~30 cyc serialized per warp
// (R7: 4 coll -> 122 cyc/step; R11: 3 coll + extra work -> ~165). So cut to
// ONE collective per argmax: m = REDUX.max(key); every lane whose key equals
// m stores its own token (predicated STS, same address -> one HW write).
// Tie-break soundness: winner idx only affects the trajectory when s=1
// (s=0 -> gather scaled by 0). Ties with s=1 need bit-identical membranes
// >= vth>0 -- the structural all-zero ties have m=0 < vth (s=0, idx moot),
// and positive bit-exact ties are measure-zero for this data. rel_err is the
// canary: it must stay exactly 4.882994e-08.
//
// Everything else frozen from R11: decoupled dataflow (B: L0 chunk c + L2
// [0,96) chunk c-2; A: L1 chunk c-1 + L2 [96,128) chunk c-2), 80-step
// double-buffered token streams, token prefetch groups of 8, packed W2
// layouts, __launch_bounds__(128,1), no "memory" clobber on asm stores.

#define NB    256
#define NCH   32
#define NT    4000
#define CHUNK 80
#define NCHK  (NT / CHUNK)     // 50
#define NBLK8 (NT / 8)         // 500

__device__ __align__(16) float  g_W1T[32 * 64];    // W1T[c][j] = W1[j][c]
__device__ __align__(16) float4 g_W2B[64 * 32];    // [idx1][lane] = (n2l, n2l+1, n64+l, 0)
__device__ __align__(16) float  g_W2A[64 * 32];    // [idx1][lane] = n96+l

__global__ void prep_kernel(const float* __restrict__ W1, const float* __restrict__ W2) {
    int tid = blockIdx.x * blockDim.x + threadIdx.x;
    int nthr = blockDim.x * gridDim.x;
    for (int i = tid; i < 64 * 32; i += nthr) {
        int r = i >> 5, c = i & 31;
        g_W1T[c * 64 + r] = W1[i];          // W1 is [64][32]
    }
    for (int i = tid; i < 64 * 32; i += nthr) {
        int c = i >> 5, l = i & 31;         // c = idx1 (W2 column), l = lane
        float4 v;
        v.x = W2[(2 * l)     * 64 + c];
        v.y = W2[(2 * l + 1) * 64 + c];
        v.z = W2[(64 + l)    * 64 + c];
        v.w = 0.0f;
        g_W2B[i] = v;
        g_W2A[i] = W2[(96 + l) * 64 + c];
    }
}

// Correctly-rounded division by constant c (rc = RN(1/c)), Markstein sequence.
__device__ __forceinline__ float divc(float v, float c, float rc) {
    float q = v * rc;
    float r = __fmaf_rn(-c, q, v);
    return __fmaf_rn(r, rc, q);
}

// Monotone key: strictly order-preserving float -> unsigned mapping.
__device__ __forceinline__ unsigned fkey(float v) {
    unsigned b = __float_as_uint(v);
    return b ^ ((unsigned)((int)b >> 31) | 0x80000000u);
}

// key(1.5f): 0x3FC00000 -> 0xBFC00000 ; key(1.2f): 0x3F99999A -> 0xBF99999A
#define KEY_VTH0 0xBFC00000u
#define KEY_VTH1 0xBF99999Au

__device__ __forceinline__ unsigned smem_u32(const void* p) {
    unsigned r;
    asm("{ .reg .u64 t; cvta.to.shared.u64 t, %1; cvt.u32.u64 %0, t; }"
        : "=r"(r) : "l"(p));
    return r;
}

// Predicated shared store (no BSSY, no "memory" clobber -- R10 lesson).
__device__ __forceinline__ void sts_if(unsigned cond, unsigned addr, unsigned val) {
    asm volatile(
        "{\n\t"
        ".reg .pred p;\n\t"
        "setp.ne.u32 p, %0, 0;\n\t"
        "@p st.shared.u32 [%1], %2;\n\t"
        "}"
        :: "r"(cond), "r"(addr), "r"(val));
}

__global__ void __launch_bounds__(128, 1)
lsm_kernel(const float* __restrict__ x, float* __restrict__ out) {
    // token streams: [sample][buffer][step-in-chunk]
    __shared__ unsigned s0tok[2][2][CHUNK];
    __shared__ unsigned s1tok[2][2][CHUNK];

    const int tid  = threadIdx.x;
    const int lane = tid & 31;
    const int warp = tid >> 5;
    const int samp = warp & 1;
    const int roleB = (warp >= 2);      // B = L0 producer + L2[0:96); A = L1 + L2[96:128)
    const int b    = (blockIdx.x << 1) + samp;

    const float RCT = 1.0f / 80000.0f;

    // --- B state ---
    float v0 = 0.0f;
    float v2x = 0.0f, v2y = 0.0f, v2z = 0.0f;   // neurons 2l, 2l+1, 64+l
    float pcx = 0.0f, pcy = 0.0f, pcz = 0.0f;
    float4 c0, c1;
    int gblk = 0;
    // --- A state ---
    float v1a = 0.0f, v1b = 0.0f;
    float v2w = 0.0f, pcw = 0.0f;               // neuron 96+l

    const float4* xp   = reinterpret_cast<const float4*>(x + (size_t)b * (NCH * NT) + lane * NT);
    const float2* w1p  = reinterpret_cast<const float2*>(g_W1T);
    const float4* w2bp = g_W2B;
    const float*  w2ap = g_W2A;

    if (roleB) { c0 = __ldg(xp); c1 = __ldg(xp + 1); }

    for (int c = 0; c <= NCHK + 1; ++c) {
        if (roleB) {
            // ---- B: L0 chunk c (produce s0 tokens; 1 REDUX/step) ----
            if (c < NCHK) {
                unsigned tba = smem_u32(&s0tok[samp][c & 1][0]);
                for (int k = 0; k < CHUNK / 8; ++k) {
                    int nb = (gblk + 1 < NBLK8) ? (gblk + 1) * 2 : 0;
                    float4 n0 = __ldg(xp + nb);
                    float4 n1 = __ldg(xp + nb + 1);
                    float xs[8] = {c0.x, c0.y, c0.z, c0.w, c1.x, c1.y, c1.z, c1.w};
#pragma unroll
                    for (int j = 0; j < 8; ++j) {
                        float d0  = divc(v0, 3.0f, 1.0f / 3.0f);
                        float ch0 = (v0 + xs[j]) - d0;
                        unsigned k0 = fkey(ch0);
                        unsigned m0 = __reduce_max_sync(0xFFFFFFFFu, k0);
                        unsigned tok = (unsigned)lane | ((m0 >= KEY_VTH0) ? 0x80000000u : 0u);
                        // all max-lanes store their own token; one HW write wins
                        sts_if((unsigned)(k0 == m0), tba + (unsigned)((k * 8 + j) * 4), tok);
                        v0 = (ch0 >= 1.5f) ? 0.0f : ch0;
                    }
                    c0 = n0; c1 = n1; ++gblk;
                }
            }
            // ---- B: L2 neurons [0,96) chunk c-2 (no collectives) ----
            if (c >= 2) {
                const unsigned* sb = &s1tok[samp][c & 1][0];
                for (int k = 0; k < CHUNK / 8; ++k) {
                    unsigned toks[8];
#pragma unroll
                    for (int j = 0; j < 8; ++j) toks[j] = sb[k * 8 + j];
#pragma unroll
                    for (int j = 0; j < 8; ++j) {
                        unsigned idx1 = toks[j] & 0x7FFFFFFFu;
                        float s1 = (toks[j] & 0x80000000u) ? 1.0f : 0.0f;
                        float4 w = __ldg(w2bp + (idx1 << 5) + lane);   // n 2l,2l+1,64+l
                        float dx = divc(v2x, 80000.0f, RCT);
                        float dy = divc(v2y, 80000.0f, RCT);
                        float dz = divc(v2z, 80000.0f, RCT);
                        pcx = __fmaf_rn(w.x, s1, v2x) - dx;
                        pcy = __fmaf_rn(w.y, s1, v2y) - dy;
                        pcz = __fmaf_rn(w.z, s1, v2z) - dz;
                        v2x = (pcx >= 1.2f) ? 0.0f : pcx;
                        v2y = (pcy >= 1.2f) ? 0.0f : pcy;
                        v2z = (pcz >= 1.2f) ? 0.0f : pcz;
                    }
                }
            }
        } else {
            // ---- A: L1 chunk c-1 (s0 toks -> s1 toks; 1 REDUX/step) ----
            if (c >= 1 && c <= NCHK) {
                const unsigned* sb = &s0tok[samp][(c - 1) & 1][0];
                unsigned tba = smem_u32(&s1tok[samp][(c - 1) & 1][0]);
                for (int k = 0; k < CHUNK / 8; ++k) {
                    unsigned toks[8];
#pragma unroll
                    for (int j = 0; j < 8; ++j) toks[j] = sb[k * 8 + j];
#pragma unroll
                    for (int j = 0; j < 8; ++j) {
                        unsigned idx0 = toks[j] & 0x7FFFFFFFu;
                        float s0 = (toks[j] & 0x80000000u) ? 1.0f : 0.0f;
                        float2 w1 = __ldg(w1p + (idx0 << 5) + lane);   // W1T[idx0][2l..2l+1]
                        float d1a = divc(v1a, 80000.0f, RCT);
                        float d1b = divc(v1b, 80000.0f, RCT);
                        float cha = __fmaf_rn(w1.x, s0, v1a) - d1a;    // exact: s0 in {0,1}
                        float chb = __fmaf_rn(w1.y, s0, v1b) - d1b;
                        unsigned ka = fkey(cha);
                        unsigned kb = fkey(chb);
                        bool bw = kb > ka;                  // local pair select
                        unsigned lk = bw ? kb : ka;
                        unsigned li = 2u * (unsigned)lane + (bw ? 1u : 0u);
                        unsigned m1 = __reduce_max_sync(0xFFFFFFFFu, lk);
                        unsigned tok1 = li | ((m1 >= KEY_VTH1) ? 0x80000000u : 0u);
                        sts_if((unsigned)(lk == m1), tba + (unsigned)((k * 8 + j) * 4), tok1);
                        v1a = (cha >= 1.2f) ? 0.0f : cha;
                        v1b = (chb >= 1.2f) ? 0.0f : chb;
                    }
                }
            }
            // ---- A: L2 neurons [96,128) chunk c-2 (no collectives) ----
            if (c >= 2) {
                const unsigned* sb = &s1tok[samp][c & 1][0];
                for (int k = 0; k < CHUNK / 8; ++k) {
                    unsigned toks[8];
#pragma unroll
                    for (int j = 0; j < 8; ++j) toks[j] = sb[k * 8 + j];
#pragma unroll
                    for (int j = 0; j < 8; ++j) {
                        unsigned idx1 = toks[j] & 0x7FFFFFFFu;
                        float s1 = (toks[j] & 0x80000000u) ? 1.0f : 0.0f;
                        float whi = __ldg(w2ap + (idx1 << 5) + lane);  // n 96+l
                        float dw = divc(v2w, 80000.0f, RCT);
                        pcw = __fmaf_rn(whi, s1, v2w) - dw;
                        v2w = (pcw >= 1.2f) ? 0.0f : pcw;
                    }
                }
            }
        }
        __syncthreads();
    }

    // Output: liquid state = exp(pre-reset v2 at step NT-1). Disjoint ranges.
    float* ob = out + (size_t)b * 128;
    if (roleB) {
        float2 o2; o2.x = expf(pcx); o2.y = expf(pcy);
        reinterpret_cast<float2*>(ob)[lane] = o2;        // neurons 2l, 2l+1
        ob[64 + lane] = expf(pcz);                       // neuron 64+l
    } else {
        ob[96 + lane] = expf(pcw);                       // neuron 96+l
    }
}

extern "C" void kernel_launch(void* const* d_in, const int* in_sizes, int n_in,
                              void* d_out, int out_size) {
    const float* x  = (const float*)d_in[0];
    const float* W1 = (const float*)d_in[1];
    const float* W2 = (const float*)d_in[2];
    float* out = (float*)d_out;

    prep_kernel<<<1, 256>>>(W1, W2);
    lsm_kernel<<<NB / 2, 128>>>(x, out);
}

// round 13
// speedup vs baseline: 1.4284x; 1.4284x over previous
#include <cuda_runtime.h>

// EEG_SimpleLSM: 3-layer LIF winner-take-all liquid state machine.
// x: [256, 32, 4000] f32, W1: [64,32], W2: [128,64]. Output: exp(pre_v2@T-1) [256,128].
//
// ROUND 13. Stage-level fit of R1-12: L2full~120, L0~73, L1~90 cyc/step; the
// L2/L1 cost is UNHOISTED gather latency (token LDS 29 -> weight LDG ~40
// issued inside the compute loop), not collectives. Fixes:
//  1. Explicit weight prefetch: per 8-step group, a pre-pass loads the 8
//     dependent weight vectors (idx from prefetched tokens) BEFORE compute.
//  2. 3 warps per sample (192 thr/CTA, grid 128): dedicated L0/L1/L2 warps,
//     chunk-skewed c / c-1 / c-2. Bottleneck = slowest single stage.
//     Warp map (role=warp>>1, samp=warp&1): SMSP0/1 = L0+L2, SMSP2/3 = L1
//     alone. L2 reads one packed float4 (neurons 2l,2l+1,64+l,96+l) from
//     g_W2F.
// Retained: 80-step double-buffered token streams (52 barriers), same-step
// token consumption (L1 step t eats s0(t); L2 step t eats s1(t) -- no drain:
// L0 c=0..49, L1 c=1..50, L2 c=2..51), single-collective argmax with
// predicated same-address store (R12, rel_err-validated), no "memory"
// clobber, __launch_bounds__(192,1). All charge/reset arithmetic bit-identical
// to R3..R12 -> rel_err must remain exactly 4.882994e-08.

#define NB    256
#define NCH   32
#define NT    4000
#define CHUNK 80
#define NCHK  (NT / CHUNK)     // 50
#define NBLK8 (NT / 8)         // 500

__device__ __align__(16) float  g_W1T[32 * 64];    // [idx0][2l..2l+1] pairs
__device__ __align__(16) float4 g_W2F[64 * 32];    // [idx1][lane] = (n2l, n2l+1, n64+l, n96+l)

__global__ void prep_kernel(const float* __restrict__ W1, const float* __restrict__ W2) {
    int tid = blockIdx.x * blockDim.x + threadIdx.x;
    int nthr = blockDim.x * gridDim.x;
    for (int i = tid; i < 64 * 32; i += nthr) {
        int r = i >> 5, c = i & 31;
        g_W1T[c * 64 + r] = W1[i];          // W1 is [64][32]
    }
    for (int i = tid; i < 64 * 32; i += nthr) {
        int c = i >> 5, l = i & 31;         // c = idx1 (W2 column), l = lane
        float4 v;
        v.x = W2[(2 * l)     * 64 + c];
        v.y = W2[(2 * l + 1) * 64 + c];
        v.z = W2[(64 + l)    * 64 + c];
        v.w = W2[(96 + l)    * 64 + c];
        g_W2F[i] = v;
    }
}

// Correctly-rounded division by constant c (rc = RN(1/c)), Markstein sequence.
__device__ __forceinline__ float divc(float v, float c, float rc) {
    float q = v * rc;
    float r = __fmaf_rn(-c, q, v);
    return __fmaf_rn(r, rc, q);
}

// Monotone key: strictly order-preserving float -> unsigned mapping.
__device__ __forceinline__ unsigned fkey(float v) {
    unsigned b = __float_as_uint(v);
    return b ^ ((unsigned)((int)b >> 31) | 0x80000000u);
}

// key(1.5f): 0x3FC00000 -> 0xBFC00000 ; key(1.2f): 0x3F99999A -> 0xBF99999A
#define KEY_VTH0 0xBFC00000u
#define KEY_VTH1 0xBF99999Au

__device__ __forceinline__ unsigned smem_u32(const void* p) {
    unsigned r;
    asm("{ .reg .u64 t; cvta.to.shared.u64 t, %1; cvt.u32.u64 %0, t; }"
        : "=r"(r) : "l"(p));
    return r;
}

// Predicated shared store (no BSSY, no "memory" clobber).
__device__ __forceinline__ void sts_if(unsigned cond, unsigned addr, unsigned val) {
    asm volatile(
        "{\n\t"
        ".reg .pred p;\n\t"
        "setp.ne.u32 p, %0, 0;\n\t"
        "@p st.shared.u32 [%1], %2;\n\t"
        "}"
        :: "r"(cond), "r"(addr), "r"(val));
}

__global__ void __launch_bounds__(192, 1)
lsm_kernel(const float* __restrict__ x, float* __restrict__ out) {
    // token streams: [sample][buffer][step-in-chunk]
    __shared__ unsigned s0tok[2][2][CHUNK];
    __shared__ unsigned s1tok[2][2][CHUNK];

    const int tid  = threadIdx.x;
    const int lane = tid & 31;
    const int warp = tid >> 5;
    const int samp = warp & 1;
    const int role = warp >> 1;     // 0 = L0, 1 = L1, 2 = L2
    const int b    = (blockIdx.x << 1) + samp;

    const float RCT = 1.0f / 80000.0f;

    // --- L0 state ---
    float v0 = 0.0f;
    float4 c0, c1;
    int gblk = 0;
    // --- L1 state ---
    float v1a = 0.0f, v1b = 0.0f;
    // --- L2 state ---
    float4 v2 = make_float4(0.f, 0.f, 0.f, 0.f);
    float4 pc = make_float4(0.f, 0.f, 0.f, 0.f);

    const float4* xp  = reinterpret_cast<const float4*>(x + (size_t)b * (NCH * NT) + lane * NT);
    const float2* w1p = reinterpret_cast<const float2*>(g_W1T);
    const float4* w2p = g_W2F;

    if (role == 0) { c0 = __ldg(xp); c1 = __ldg(xp + 1); }

    for (int c = 0; c <= NCHK + 1; ++c) {
        if (role == 0) {
            // ---- L0 chunk c: produce s0 tokens ----
            if (c < NCHK) {
                unsigned tba = smem_u32(&s0tok[samp][c & 1][0]);
                for (int k = 0; k < CHUNK / 8; ++k) {
                    int nb = (gblk + 1 < NBLK8) ? (gblk + 1) * 2 : 0;
                    float4 n0 = __ldg(xp + nb);
                    float4 n1 = __ldg(xp + nb + 1);
                    float xs[8] = {c0.x, c0.y, c0.z, c0.w, c1.x, c1.y, c1.z, c1.w};
#pragma unroll
                    for (int j = 0; j < 8; ++j) {
                        float d0  = divc(v0, 3.0f, 1.0f / 3.0f);
                        float ch0 = (v0 + xs[j]) - d0;
                        unsigned k0 = fkey(ch0);
                        unsigned m0 = __reduce_max_sync(0xFFFFFFFFu, k0);
                        unsigned tok = (unsigned)lane | ((m0 >= KEY_VTH0) ? 0x80000000u : 0u);
                        sts_if((unsigned)(k0 == m0), tba + (unsigned)((k * 8 + j) * 4), tok);
                        v0 = (ch0 >= 1.5f) ? 0.0f : ch0;
                    }
                    c0 = n0; c1 = n1; ++gblk;
                }
            }
        } else if (role == 1) {
            // ---- L1 chunk c-1: consume s0 tokens, produce s1 tokens ----
            if (c >= 1 && c <= NCHK) {
                const unsigned* sb = &s0tok[samp][(c - 1) & 1][0];
                unsigned tba = smem_u32(&s1tok[samp][(c - 1) & 1][0]);
                for (int k = 0; k < CHUNK / 8; ++k) {
                    unsigned toks[8];
                    float2 wv[8];
#pragma unroll
                    for (int j = 0; j < 8; ++j) toks[j] = sb[k * 8 + j];
#pragma unroll
                    for (int j = 0; j < 8; ++j)    // weight prefetch (MLP=8)
                        wv[j] = __ldg(w1p + ((toks[j] & 0x7FFFFFFFu) << 5) + lane);
#pragma unroll
                    for (int j = 0; j < 8; ++j) {
                        float s0 = (toks[j] & 0x80000000u) ? 1.0f : 0.0f;
                        float d1a = divc(v1a, 80000.0f, RCT);
                        float d1b = divc(v1b, 80000.0f, RCT);
                        float cha = __fmaf_rn(wv[j].x, s0, v1a) - d1a;  // exact: s0 in {0,1}
                        float chb = __fmaf_rn(wv[j].y, s0, v1b) - d1b;
                        unsigned ka = fkey(cha);
                        unsigned kb = fkey(chb);
                        bool bw = kb > ka;
                        unsigned lk = bw ? kb : ka;
                        unsigned li = 2u * (unsigned)lane + (bw ? 1u : 0u);
                        unsigned m1 = __reduce_max_sync(0xFFFFFFFFu, lk);
                        unsigned tok1 = li | ((m1 >= KEY_VTH1) ? 0x80000000u : 0u);
                        sts_if((unsigned)(lk == m1), tba + (unsigned)((k * 8 + j) * 4), tok1);
                        v1a = (cha >= 1.2f) ? 0.0f : cha;
                        v1b = (chb >= 1.2f) ? 0.0f : chb;
                    }
                }
            }
        } else {
            // ---- L2 chunk c-2: consume s1 tokens ----
            if (c >= 2) {
                const unsigned* sb = &s1tok[samp][c & 1][0];
                for (int k = 0; k < CHUNK / 8; ++k) {
                    unsigned toks[8];
                    float4 wv[8];
#pragma unroll
                    for (int j = 0; j < 8; ++j) toks[j] = sb[k * 8 + j];
#pragma unroll
                    for (int j = 0; j < 8; ++j)    // weight prefetch (MLP=8)
                        wv[j] = __ldg(w2p + ((toks[j] & 0x7FFFFFFFu) << 5) + lane);
#pragma unroll
                    for (int j = 0; j < 8; ++j) {
                        float s1 = (toks[j] & 0x80000000u) ? 1.0f : 0.0f;
                        float dx = divc(v2.x, 80000.0f, RCT);
                        float dy = divc(v2.y, 80000.0f, RCT);
                        float dz = divc(v2.z, 80000.0f, RCT);
                        float dw = divc(v2.w, 80000.0f, RCT);
                        pc.x = __fmaf_rn(wv[j].x, s1, v2.x) - dx;
                        pc.y = __fmaf_rn(wv[j].y, s1, v2.y) - dy;
                        pc.z = __fmaf_rn(wv[j].z, s1, v2.z) - dz;
                        pc.w = __fmaf_rn(wv[j].w, s1, v2.w) - dw;
                        v2.x = (pc.x >= 1.2f) ? 0.0f : pc.x;
                        v2.y = (pc.y >= 1.2f) ? 0.0f : pc.y;
                        v2.z = (pc.z >= 1.2f) ? 0.0f : pc.z;
                        v2.w = (pc.w >= 1.2f) ? 0.0f : pc.w;
                    }
                }
            }
        }
        __syncthreads();
    }

    // Output: liquid state = exp(pre-reset v2 at step NT-1). L2 warp owns all.
    if (role == 2) {
        float* ob = out + (size_t)b * 128;
        float2 o2; o2.x = expf(pc.x); o2.y = expf(pc.y);
        reinterpret_cast<float2*>(ob)[lane] = o2;        // neurons 2l, 2l+1
        ob[64 + lane] = expf(pc.z);                      // neuron 64+l
        ob[96 + lane] = expf(pc.w);                      // neuron 96+l
    }
}

extern "C" void kernel_launch(void* const* d_in, const int* in_sizes, int n_in,
                              void* d_out, int out_size) {
    const float* x  = (const float*)d_in[0];
    const float* W1 = (const float*)d_in[1];
    const float* W2 = (const float*)d_in[2];
    float* out = (float*)d_out;

    prep_kernel<<<1, 256>>>(W1, W2);
    lsm_kernel<<<NB / 2, 192>>>(x, out);
}